// round 13
// baseline (speedup 1.0000x reference)
#include <cuda_runtime.h>
#include <cuda_fp16.h>
#include <math.h>
#include <stdint.h>

// Problem constants
#define S_LEN   2048
#define BATCH   2
#define DMODEL  1024
#define NHEADS  16
#define DHEAD   64
#define CLEN    16
#define BHT     32
#define MROWS   4096
#define NCH     32
#define CHLEN   64
#define DM2E    (DMODEL * DMODEL)

// fp16 storage offsets (elements)
#define OFF_X   0
#define OFF_W   (MROWS * DMODEL)
#define OFF_O   (OFF_W + 4 * DMODEL * DMODEL)
#define BF_TOT  (OFF_O + MROWS * DMODEL)

#define XN4     (MROWS * DMODEL / 4)
#define WN4     (DMODEL * DMODEL / 4)

// GEMM smem geometry: 2 tiles (A,B) x 128 rows x (128B data + 16B pad) per stage
#define ROWB    144
#define TILEB   (128 * ROWB)        // 18432
#define STAGEB  (2 * TILEB)         // 36864
#define NSTAGE  2
#define GSMEM   (NSTAGE * STAGEB)   // 73728 bytes -> 2 CTAs/SM (147KB)
#define NKC     16                  // 16 chunks of 64 K-elements

// scan smem layout (floats)
#define SCQ     0
#define SCKT    4160
#define SCG     8512
#define SCW     12672
#define SCC     13952
#define SCD     15232
#define SCNB    16320
#define SCDEN   18400
#define SCTOT   18416

// Scratch
__device__ __align__(256) float g_Q[MROWS * DMODEL];
__device__ __align__(256) float g_K[MROWS * DMODEL];
__device__ __align__(256) float g_V[MROWS * DMODEL];
__device__ __align__(256) float g_Wt[BHT * S_LEN * CLEN];
__device__ __align__(256) unsigned int g_LmaxI[BHT * CLEN];
__device__ __align__(256) float g_Psum[BHT * NCH * CLEN * 128];
__device__ __align__(256) float g_Pden[BHT * NCH * CLEN];
__device__ __align__(256) __half g_hi[BF_TOT];

// ---------------------------------------------------------------------------
__device__ __forceinline__ uint32_t smem_u32(const void* p) {
    uint32_t a;
    asm("{ .reg .u64 t; cvta.to.shared.u64 t, %1; cvt.u32.u64 %0, t; }" : "=r"(a) : "l"(p));
    return a;
}
#define CP16(dst, src) \
    asm volatile("cp.async.cg.shared.global [%0], [%1], 16;" :: "r"(dst), "l"(src))
#define CP_COMMIT() asm volatile("cp.async.commit_group;" ::: "memory")
#define CP_WAIT0()  asm volatile("cp.async.wait_group 0;" ::: "memory")
#define CP_WAIT1()  asm volatile("cp.async.wait_group 1;" ::: "memory")

#define LDSM4(r0, r1, r2, r3, addr) \
    asm volatile("ldmatrix.sync.aligned.m8n8.x4.shared.b16 {%0,%1,%2,%3}, [%4];" \
        : "=r"(r0), "=r"(r1), "=r"(r2), "=r"(r3) : "r"(addr))

__device__ __forceinline__ void mma16816(float* d, const uint32_t* a, const uint32_t* b)
{
    asm volatile(
        "mma.sync.aligned.m16n8k16.row.col.f32.f16.f16.f32 "
        "{%0,%1,%2,%3}, {%4,%5,%6,%7}, {%8,%9}, {%0,%1,%2,%3};"
        : "+f"(d[0]), "+f"(d[1]), "+f"(d[2]), "+f"(d[3])
        : "r"(a[0]), "r"(a[1]), "r"(a[2]), "r"(a[3]), "r"(b[0]), "r"(b[1]));
}

__device__ __forceinline__ unsigned int enc_max(float f) {
    unsigned int u = __float_as_uint(f);
    return (u & 0x80000000u) ? ~u : (u | 0x80000000u);
}
__device__ __forceinline__ float dec_max(unsigned int u) {
    return (u & 0x80000000u) ? __uint_as_float(u ^ 0x80000000u) : __uint_as_float(~u);
}

// ---------------------------------------------------------------------------
// Fused convert: x + 4 weights -> fp16; also zero-inits g_LmaxI.
// ---------------------------------------------------------------------------
__global__ __launch_bounds__(256)
void k_split_all(const float* __restrict__ x,  const float* __restrict__ wq,
                 const float* __restrict__ wk, const float* __restrict__ wv,
                 const float* __restrict__ wo)
{
    int gid = blockIdx.x * 256 + threadIdx.x;
    if (gid < BHT * CLEN) g_LmaxI[gid] = 0u;

    const float* src;
    size_t off;
    int local;
    if (gid < XN4) { src = x; local = gid; off = OFF_X; }
    else {
        int j = gid - XN4;
        int w = j >> 18;
        local = j & (WN4 - 1);
        src = (w == 0) ? wq : (w == 1) ? wk : (w == 2) ? wv : wo;
        off = OFF_W + (size_t)w * DM2E;
    }
    float4 a = ((const float4*)src)[local];
    __half2* hi2 = reinterpret_cast<__half2*>(g_hi + off) + 2 * local;
    hi2[0] = __halves2half2(__float2half(a.x), __float2half(a.y));
    hi2[1] = __halves2half2(__float2half(a.z), __float2half(a.w));
}

// ---------------------------------------------------------------------------
// Tensor-core GEMM, single-pass fp16, BK=64, double-buffered, 2 CTAs/SM.
// dual=1: bn>>3 selects {K,V} weight/bias/output (merged KV launch).
// ---------------------------------------------------------------------------
__global__ __launch_bounds__(256, 2)
void gemm_mma(int aoff, int boff, const float* __restrict__ bias,
              const float* __restrict__ bias2, const float* __restrict__ beta,
              int outsel, float* Outp, int qscale, int dual)
{
    extern __shared__ __align__(128) char smem_raw[];
    const uint32_t sb0 = smem_u32(smem_raw);

    const int tid = threadIdx.x;
    const int bn = blockIdx.x, bm = blockIdx.y;

    const int widx = dual ? (bn >> 3) : 0;
    const int bneff = dual ? (bn & 7) : bn;
    float* Out;
    const float* biasp;
    if (dual) { Out = widx ? g_V : g_K; biasp = widx ? bias2 : bias; }
    else      { Out = (outsel == 0) ? g_Q : Outp; biasp = bias; }

    const int warp = tid >> 5, lane = tid & 31;
    const int wm = warp & 1, wn = warp >> 1;
    const int g = lane >> 2, tig = lane & 3;

    const char* a_h = (const char*)(g_hi + aoff) + (size_t)(bm * 128) * 2048;
    const char* b_h = (const char*)(g_hi + boff + (size_t)widx * DM2E)
                    + (size_t)(bneff * 128) * 2048;

    float acc[4][4][4];
#pragma unroll
    for (int mi = 0; mi < 4; mi++)
#pragma unroll
        for (int ni = 0; ni < 4; ni++)
#pragma unroll
            for (int r = 0; r < 4; r++) acc[mi][ni][r] = 0.f;

    // cp.async mapping: 2 threads per row; each thread does 4x16B per tile.
    const int lrow = tid >> 1, lhalf = (tid & 1) * 64;

    const uint32_t a_lane = (uint32_t)(wm * 64 + (lane & 15)) * ROWB + ((lane >> 4) & 1) * 16;
    const uint32_t q4 = lane >> 3;
    const uint32_t b_lane = (uint32_t)(wn * 32 + ((q4 >> 1) & 1) * 8 + (lane & 7)) * ROWB
                          + (q4 & 1) * 16;

#define PREFETCH(kc) do { \
    uint32_t dstb = sb0 + ((kc) & 1) * STAGEB; \
    size_t kb = (size_t)(kc) * 128; \
    uint32_t doff = (uint32_t)lrow * ROWB + lhalf; \
    size_t soff = (size_t)lrow * 2048 + kb + lhalf; \
    _Pragma("unroll") \
    for (int t = 0; t < 4; t++) { \
        CP16(dstb + doff + t * 16, a_h + soff + t * 16); \
        CP16(dstb + TILEB + doff + t * 16, b_h + soff + t * 16); \
    } \
    CP_COMMIT(); } while (0)

    PREFETCH(0);

    for (int kc = 0; kc < NKC; kc++) {
        if (kc + 1 < NKC) { PREFETCH(kc + 1); CP_WAIT1(); }
        else              { CP_WAIT0(); }
        __syncthreads();

        const uint32_t st = sb0 + (kc & 1) * STAGEB;

#pragma unroll
        for (int ks = 0; ks < 4; ks++) {
            uint32_t ah[4][4], bh[4][2];
            const uint32_t abase = st + a_lane + ks * 32;
#pragma unroll
            for (int mi = 0; mi < 4; mi++)
                LDSM4(ah[mi][0], ah[mi][1], ah[mi][2], ah[mi][3], abase + mi * (16 * ROWB));
            const uint32_t bbase = st + TILEB + b_lane + ks * 32;
            LDSM4(bh[0][0], bh[0][1], bh[1][0], bh[1][1], bbase);
            LDSM4(bh[2][0], bh[2][1], bh[3][0], bh[3][1], bbase + 16 * ROWB);

#pragma unroll
            for (int mi = 0; mi < 4; mi++)
#pragma unroll
                for (int ni = 0; ni < 4; ni++)
                    mma16816(acc[mi][ni], ah[mi], bh[ni]);
        }
        __syncthreads();
    }
#undef PREFETCH

    const int ncol0 = bneff * 128 + wn * 32;
    float sc = qscale ? (1.0f / (8.0f * expf(beta[ncol0 >> 6]))) : 1.0f;
#pragma unroll
    for (int mi = 0; mi < 4; mi++) {
        int m0 = bm * 128 + wm * 64 + mi * 16 + g;
#pragma unroll
        for (int ni = 0; ni < 4; ni++) {
            int n0 = ncol0 + ni * 8 + tig * 2;
            float b0 = biasp[n0], b1 = biasp[n0 + 1];
            float2 v0, v1;
            v0.x = (acc[mi][ni][0] + b0) * sc;
            v0.y = (acc[mi][ni][1] + b1) * sc;
            v1.x = (acc[mi][ni][2] + b0) * sc;
            v1.y = (acc[mi][ni][3] + b1) * sc;
            *(float2*)(Out + (size_t)m0 * DMODEL + n0) = v0;
            *(float2*)(Out + (size_t)(m0 + 8) * DMODEL + n0) = v1;
        }
    }
}

// ---------------------------------------------------------------------------
// logits + fused per-(g,c) max
// ---------------------------------------------------------------------------
__global__ __launch_bounds__(128)
void k_logits(const float* __restrict__ qc)
{
    int g = blockIdx.y, h = g & 15, b = g >> 4;
    __shared__ float qsh[CLEN * DHEAD];
    __shared__ float redm[CLEN][128];
    for (int i = threadIdx.x; i < CLEN * DHEAD; i += 128)
        qsh[i] = qc[(i >> 6) * DMODEL + h * DHEAD + (i & 63)];
    __syncthreads();

    int tid = threadIdx.x;
    int s = blockIdx.x * 128 + tid;
    int m = s * BATCH + b;
    const float* kr = g_K + (size_t)m * DMODEL + h * DHEAD;
    float acc[CLEN];
#pragma unroll
    for (int c = 0; c < CLEN; c++) acc[c] = 0.f;
    for (int d = 0; d < DHEAD; d += 4) {
        float4 kv = *(const float4*)(kr + d);
#pragma unroll
        for (int c = 0; c < CLEN; c++) {
            acc[c] = fmaf(qsh[c * 64 + d + 0], kv.x, acc[c]);
            acc[c] = fmaf(qsh[c * 64 + d + 1], kv.y, acc[c]);
            acc[c] = fmaf(qsh[c * 64 + d + 2], kv.z, acc[c]);
            acc[c] = fmaf(qsh[c * 64 + d + 3], kv.w, acc[c]);
        }
    }
    float* wp = g_Wt + ((size_t)g * S_LEN + s) * CLEN;
#pragma unroll
    for (int c = 0; c < CLEN; c++) { wp[c] = acc[c]; redm[c][tid] = acc[c]; }
    __syncthreads();

    int w = tid >> 5, lane = tid & 31;
#pragma unroll
    for (int cc = 0; cc < 4; cc++) {
        int c = w * 4 + cc;
        float v = fmaxf(fmaxf(redm[c][lane], redm[c][lane + 32]),
                        fmaxf(redm[c][lane + 64], redm[c][lane + 96]));
        v = fmaxf(v, __shfl_xor_sync(0xffffffffu, v, 16));
        v = fmaxf(v, __shfl_xor_sync(0xffffffffu, v, 8));
        v = fmaxf(v, __shfl_xor_sync(0xffffffffu, v, 4));
        v = fmaxf(v, __shfl_xor_sync(0xffffffffu, v, 2));
        v = fmaxf(v, __shfl_xor_sync(0xffffffffu, v, 1));
        if (lane == 0) atomicMax(&g_LmaxI[g * CLEN + c], enc_max(v));
    }
}

// ---------------------------------------------------------------------------
// Chunk partial sums, barrier-free mainloop
// ---------------------------------------------------------------------------
__global__ __launch_bounds__(128)
void k_chunksum_mm()
{
    __shared__ float Wsh[64 * 20];
    int g = blockIdx.y, cx = blockIdx.x;
    int b = g >> 4, h = g & 15;
    int tid = threadIdx.x, d = tid;

    {
        int t = tid >> 1, c0 = (tid & 1) * 8;
#pragma unroll
        for (int j = 0; j < 8; j++) {
            int c = c0 + j;
            float lm = dec_max(g_LmaxI[g * CLEN + c]);
            float lg = g_Wt[((size_t)g * S_LEN + cx * 64 + t) * CLEN + c];
            Wsh[t * 20 + c] = expf(lg - lm);
        }
    }
    __syncthreads();

    const float* kvb = ((d < 64) ? g_K : g_V) + (size_t)b * DMODEL + h * DHEAD + (d & 63);
    float acc[16];
#pragma unroll
    for (int c = 0; c < 16; c++) acc[c] = 0.f;

    for (int t = 0; t < 64; t += 4) {
        float kvr[4];
#pragma unroll
        for (int i = 0; i < 4; i++)
            kvr[i] = kvb[(size_t)(cx * 64 + t + i) * 2048];
#pragma unroll
        for (int i = 0; i < 4; i++) {
            float4 wv[4];
            const float4* w4 = (const float4*)&Wsh[(t + i) * 20];
            wv[0] = w4[0]; wv[1] = w4[1]; wv[2] = w4[2]; wv[3] = w4[3];
            const float* wf = (const float*)wv;
            float kv = kvr[i];
#pragma unroll
            for (int c = 0; c < 16; c++) acc[c] = fmaf(wf[c], kv, acc[c]);
        }
    }
    float* ps = g_Psum + ((size_t)(g * NCH + cx) * CLEN) * 128;
#pragma unroll
    for (int c = 0; c < 16; c++) ps[c * 128 + d] = acc[c];
    if (tid < CLEN) {
        float r = 0.f;
        for (int t = 0; t < 64; t++) r += Wsh[t * 20 + tid];
        g_Pden[(g * NCH + cx) * CLEN + tid] = r;
    }
}

// ---------------------------------------------------------------------------
// In-place inclusive prefix over chunks (per g)
// ---------------------------------------------------------------------------
__global__ __launch_bounds__(128)
void k_prefix()
{
    int g = blockIdx.x, d = threadIdx.x;
    float run[16];
#pragma unroll
    for (int c = 0; c < 16; c++) run[c] = 0.f;
    for (int cx = 0; cx < NCH; cx++) {
        float* base = g_Psum + ((size_t)(g * NCH + cx) * CLEN) * 128;
#pragma unroll
        for (int c = 0; c < 16; c++) {
            run[c] += base[c * 128 + d];
            base[c * 128 + d] = run[c];
        }
    }
    if (d < CLEN) {
        float r = 0.f;
        for (int cx = 0; cx < NCH; cx++) {
            r += g_Pden[(g * NCH + cx) * CLEN + d];
            g_Pden[(g * NCH + cx) * CLEN + d] = r;
        }
    }
}

// ---------------------------------------------------------------------------
// Matrix-form scan + attention epilogue
// ---------------------------------------------------------------------------
__global__ __launch_bounds__(128)
void k_scan_mm()
{
    extern __shared__ float sm[];
    int g = blockIdx.y, cx = blockIdx.x;
    int b = g >> 4, h = g & 15;
    int tid = threadIdx.x;

    {
        int t = tid >> 1, c0 = (tid & 1) * 8;
#pragma unroll
        for (int j = 0; j < 8; j++) {
            int c = c0 + j;
            float lm = dec_max(g_LmaxI[g * CLEN + c]);
            float lg = g_Wt[((size_t)g * S_LEN + cx * 64 + t) * CLEN + c];
            sm[SCW + t * 20 + c] = expf(lg - lm);
        }
    }
#pragma unroll
    for (int i = 0; i < 8; i++) {
        int fidx = i * 128 + tid;
        int row = fidx >> 4, c4 = fidx & 15;
        int m = (cx * 64 + row) * BATCH + b;
        float4 qv = *(const float4*)(g_Q + (size_t)m * DMODEL + h * DHEAD + c4 * 4);
        sm[SCQ + row * 65 + c4 * 4 + 0] = qv.x;
        sm[SCQ + row * 65 + c4 * 4 + 1] = qv.y;
        sm[SCQ + row * 65 + c4 * 4 + 2] = qv.z;
        sm[SCQ + row * 65 + c4 * 4 + 3] = qv.w;
        float4 kv = *(const float4*)(g_K + (size_t)m * DMODEL + h * DHEAD + c4 * 4);
        sm[SCKT + (c4 * 4 + 0) * 68 + row] = kv.x;
        sm[SCKT + (c4 * 4 + 1) * 68 + row] = kv.y;
        sm[SCKT + (c4 * 4 + 2) * 68 + row] = kv.z;
        sm[SCKT + (c4 * 4 + 3) * 68 + row] = kv.w;
    }
    {
        int d = tid;
#pragma unroll
        for (int c = 0; c < CLEN; c++) {
            float v = 0.f;
            if (cx > 0)
                v = g_Psum[((size_t)(g * NCH + cx - 1) * CLEN + c) * 128 + d];
            sm[SCNB + c * 130 + d] = v;
        }
        if (tid < CLEN)
            sm[SCDEN + tid] = (cx > 0) ? g_Pden[(g * NCH + cx - 1) * CLEN + tid] : 0.f;
    }
    __syncthreads();

    {
        int slg = tid >> 3, tg = tid & 7;
        int sl0 = slg * 4, t0 = tg * 8;
        float acc[4][8];
#pragma unroll
        for (int i = 0; i < 4; i++)
#pragma unroll
            for (int j = 0; j < 8; j++) acc[i][j] = 0.f;
        for (int d = 0; d < 64; d++) {
            float q[4];
#pragma unroll
            for (int i = 0; i < 4; i++) q[i] = sm[SCQ + (sl0 + i) * 65 + d];
            float4 kv2[2];
            const float4* kt4 = (const float4*)&sm[SCKT + d * 68 + t0];
            kv2[0] = kt4[0]; kv2[1] = kt4[1];
            const float* kt = (const float*)kv2;
#pragma unroll
            for (int i = 0; i < 4; i++)
#pragma unroll
                for (int j = 0; j < 8; j++)
                    acc[i][j] = fmaf(q[i], kt[j], acc[i][j]);
        }
#pragma unroll
        for (int i = 0; i < 4; i++)
#pragma unroll
            for (int j = 0; j < 8; j++)
                sm[SCG + (sl0 + i) * 65 + t0 + j] = acc[i][j];
    }
    __syncthreads();

    {
        int sl = tid & 63, ch = tid >> 6, c0 = ch * 8;
        float a[8];
#pragma unroll
        for (int j = 0; j < 8; j++) a[j] = 0.f;
        for (int d = 0; d < 64; d++) {
            float q = sm[SCQ + sl * 65 + d];
#pragma unroll
            for (int j = 0; j < 8; j++)
                a[j] = fmaf(q, sm[SCNB + (c0 + j) * 130 + d], a[j]);
        }
        for (int t = 0; t <= sl; t++) {
            float gg = sm[SCG + sl * 65 + t];
            float4 wv[2];
            const float4* w4 = (const float4*)&sm[SCW + t * 20 + c0];
            wv[0] = w4[0]; wv[1] = w4[1];
            const float* wf = (const float*)wv;
#pragma unroll
            for (int j = 0; j < 8; j++)
                a[j] = fmaf(wf[j], gg, a[j]);
        }
#pragma unroll
        for (int j = 0; j < 8; j++) sm[SCC + sl * 20 + c0 + j] = a[j];

        if (tid < CLEN) {
            int c = tid;
            float r = sm[SCDEN + c];
            for (int t = 0; t < 64; t++) {
                r += sm[SCW + t * 20 + c];
                sm[SCD + t * 17 + c] = r;
            }
        }
    }
    __syncthreads();

#pragma unroll
    for (int i = 0; i < 8; i++) {
        int fidx = i * 128 + tid;
        int row = fidx >> 4, c4 = fidx & 15;
        int m = (cx * 64 + row) * BATCH + b;
        float4 vv = *(const float4*)(g_V + (size_t)m * DMODEL + h * DHEAD + c4 * 4);
        sm[SCQ + (c4 * 4 + 0) * 65 + row] = vv.x;
        sm[SCQ + (c4 * 4 + 1) * 65 + row] = vv.y;
        sm[SCQ + (c4 * 4 + 2) * 65 + row] = vv.z;
        sm[SCQ + (c4 * 4 + 3) * 65 + row] = vv.w;
    }
    if (tid < 64) {
        int sl = tid;
        float av[16], mx = -3.0e38f;
#pragma unroll
        for (int c = 0; c < 16; c++) {
            float aa = sm[SCC + sl * 20 + c] / sm[SCD + sl * 17 + c];
            av[c] = aa;
            mx = fmaxf(mx, aa);
        }
        float ssum = 0.f;
#pragma unroll
        for (int c = 0; c < 16; c++) { av[c] = expf(av[c] - mx); ssum += av[c]; }
        float inv = 1.0f / ssum;
#pragma unroll
        for (int c = 0; c < 16; c++)
            sm[SCC + sl * 20 + c] = av[c] * inv / sm[SCD + sl * 17 + c];
    }
    __syncthreads();

    {
        int dp = tid & 63, slh = tid >> 6;
        float num[16];
#pragma unroll
        for (int c = 0; c < 16; c++) num[c] = sm[SCNB + c * 130 + 64 + dp];
        if (slh) {
            for (int t = 0; t < 32; t++) {
                float kv = sm[SCQ + dp * 65 + t];
                float4 wv[4];
                const float4* w4 = (const float4*)&sm[SCW + t * 20];
                wv[0] = w4[0]; wv[1] = w4[1]; wv[2] = w4[2]; wv[3] = w4[3];
                const float* wf = (const float*)wv;
#pragma unroll
                for (int c = 0; c < 16; c++) num[c] = fmaf(wf[c], kv, num[c]);
            }
        }
        for (int sl = slh * 32; sl < slh * 32 + 32; sl++) {
            float kv = sm[SCQ + dp * 65 + sl];
            float4 wv[4], pv[4];
            const float4* w4 = (const float4*)&sm[SCW + sl * 20];
            const float4* p4 = (const float4*)&sm[SCC + sl * 20];
            wv[0] = w4[0]; wv[1] = w4[1]; wv[2] = w4[2]; wv[3] = w4[3];
            pv[0] = p4[0]; pv[1] = p4[1]; pv[2] = p4[2]; pv[3] = p4[3];
            const float* wf = (const float*)wv;
            const float* pf = (const float*)pv;
            float o = 0.f;
#pragma unroll
            for (int c = 0; c < 16; c++) {
                num[c] = fmaf(wf[c], kv, num[c]);
                o = fmaf(pf[c], num[c], o);
            }
            int m = (cx * 64 + sl) * BATCH + b;
            g_hi[(size_t)OFF_O + (size_t)m * DMODEL + h * DHEAD + dp] = __float2half(o);
        }
    }
}

// ---------------------------------------------------------------------------
static cudaStream_t g_sQ;
static cudaEvent_t g_evA, g_evQ;
namespace {
struct InitRes {
    InitRes() {
        cudaFuncSetAttribute(gemm_mma, cudaFuncAttributeMaxDynamicSharedMemorySize, GSMEM);
        cudaFuncSetAttribute(k_scan_mm, cudaFuncAttributeMaxDynamicSharedMemorySize, SCTOT * 4);
        cudaStreamCreateWithFlags(&g_sQ, cudaStreamNonBlocking);
        cudaEventCreateWithFlags(&g_evA, cudaEventDisableTiming);
        cudaEventCreateWithFlags(&g_evQ, cudaEventDisableTiming);
    }
};
static InitRes g_init_res;
}

// ---------------------------------------------------------------------------
extern "C" void kernel_launch(void* const* d_in, const int* in_sizes, int n_in,
                              void* d_out, int out_size)
{
    const float* x    = (const float*)d_in[0];
    const float* q_c  = (const float*)d_in[1];
    const float* beta = (const float*)d_in[2];
    const float* Wq   = (const float*)d_in[3];
    const float* bq   = (const float*)d_in[4];
    const float* Wk   = (const float*)d_in[5];
    const float* bk   = (const float*)d_in[6];
    const float* Wv   = (const float*)d_in[7];
    const float* bv   = (const float*)d_in[8];
    const float* Wo   = (const float*)d_in[9];
    const float* bo   = (const float*)d_in[10];
    float* out = (float*)d_out;

    const int TOTQ = XN4 + 4 * WN4;

    k_split_all<<<TOTQ / 256, 256>>>(x, Wq, Wk, Wv, Wo);
    cudaEventRecord(g_evA, 0);

    // Q on side stream
    cudaStreamWaitEvent(g_sQ, g_evA, 0);
    gemm_mma<<<dim3(8, 32), 256, GSMEM, g_sQ>>>(OFF_X, OFF_W + 0 * DM2E,
                                                bq, nullptr, beta, 0, nullptr, 1, 0);
    cudaEventRecord(g_evQ, g_sQ);

    // merged K+V on main stream (bn>>3: 0->K, 1->V)
    gemm_mma<<<dim3(16, 32), 256, GSMEM>>>(OFF_X, OFF_W + 1 * DM2E,
                                           bk, bv, beta, 1, nullptr, 0, 1);

    k_logits<<<dim3(S_LEN / 128, BHT), 128>>>(q_c);
    k_chunksum_mm<<<dim3(NCH, BHT), 128>>>();
    k_prefix<<<BHT, 128>>>();

    cudaStreamWaitEvent(0, g_evQ, 0);
    k_scan_mm<<<dim3(NCH, BHT), 128, SCTOT * 4>>>();
    gemm_mma<<<dim3(8, 32), 256, GSMEM>>>(OFF_O, OFF_W + 3 * DM2E,
                                          bo, nullptr, beta, 3, out, 0, 0);
}

// round 14
// speedup vs baseline: 1.1088x; 1.1088x over previous
#include <cuda_runtime.h>
#include <cuda_fp16.h>
#include <math.h>
#include <stdint.h>

// Problem constants
#define S_LEN   2048
#define BATCH   2
#define DMODEL  1024
#define NHEADS  16
#define DHEAD   64
#define CLEN    16
#define BHT     32
#define MROWS   4096
#define NCH     32
#define CHLEN   64
#define DM2E    (DMODEL * DMODEL)

// fp16 storage offsets (elements)
#define OFF_X   0
#define OFF_W   (MROWS * DMODEL)
#define OFF_O   (OFF_W + 4 * DMODEL * DMODEL)
#define BF_TOT  (OFF_O + MROWS * DMODEL)

#define XN4     (MROWS * DMODEL / 4)
#define WN4     (DMODEL * DMODEL / 4)

// GEMM smem geometry: 2 tiles (A,B) x 128 rows x 80B/row per stage (R12 proven)
#define ROWB    80
#define TILEB   (128 * ROWB)
#define STAGEB  (2 * TILEB)
#define NSTAGE  2
#define GSMEM   (NSTAGE * STAGEB)   // 40960 bytes

// scan smem layout (floats)
#define SCQ     0
#define SCKT    4160
#define SCG     8512
#define SCW     12672
#define SCC     13952
#define SCD     15232
#define SCNB    16320
#define SCDEN   18400
#define SCTOT   18416

// Scratch
__device__ __align__(256) float g_Q[MROWS * DMODEL];
__device__ __align__(256) float g_K[MROWS * DMODEL];
__device__ __align__(256) float g_V[MROWS * DMODEL];
__device__ __align__(256) float g_Wt[BHT * S_LEN * CLEN];
__device__ __align__(256) unsigned int g_LmaxI[BHT * CLEN];
__device__ __align__(256) float g_Psum[BHT * NCH * CLEN * 128];
__device__ __align__(256) float g_Pden[BHT * NCH * CLEN];
__device__ __align__(256) __half g_hi[BF_TOT];

// ---------------------------------------------------------------------------
__device__ __forceinline__ uint32_t smem_u32(const void* p) {
    uint32_t a;
    asm("{ .reg .u64 t; cvta.to.shared.u64 t, %1; cvt.u32.u64 %0, t; }" : "=r"(a) : "l"(p));
    return a;
}
#define CP16(dst, src) \
    asm volatile("cp.async.cg.shared.global [%0], [%1], 16;" :: "r"(dst), "l"(src))
#define CP_COMMIT() asm volatile("cp.async.commit_group;" ::: "memory")
#define CP_WAIT0()  asm volatile("cp.async.wait_group 0;" ::: "memory")
#define CP_WAIT1()  asm volatile("cp.async.wait_group 1;" ::: "memory")

#define LDSM4(r0, r1, r2, r3, addr) \
    asm volatile("ldmatrix.sync.aligned.m8n8.x4.shared.b16 {%0,%1,%2,%3}, [%4];" \
        : "=r"(r0), "=r"(r1), "=r"(r2), "=r"(r3) : "r"(addr))

__device__ __forceinline__ void mma16816(float* d, const uint32_t* a, const uint32_t* b)
{
    asm volatile(
        "mma.sync.aligned.m16n8k16.row.col.f32.f16.f16.f32 "
        "{%0,%1,%2,%3}, {%4,%5,%6,%7}, {%8,%9}, {%0,%1,%2,%3};"
        : "+f"(d[0]), "+f"(d[1]), "+f"(d[2]), "+f"(d[3])
        : "r"(a[0]), "r"(a[1]), "r"(a[2]), "r"(a[3]), "r"(b[0]), "r"(b[1]));
}

__device__ __forceinline__ unsigned int enc_max(float f) {
    unsigned int u = __float_as_uint(f);
    return (u & 0x80000000u) ? ~u : (u | 0x80000000u);
}
__device__ __forceinline__ float dec_max(unsigned int u) {
    return (u & 0x80000000u) ? __uint_as_float(u ^ 0x80000000u) : __uint_as_float(~u);
}

// ---------------------------------------------------------------------------
// Fused convert: x + 4 weights -> fp16; also zero-inits g_LmaxI.
// ---------------------------------------------------------------------------
__global__ __launch_bounds__(256)
void k_split_all(const float* __restrict__ x,  const float* __restrict__ wq,
                 const float* __restrict__ wk, const float* __restrict__ wv,
                 const float* __restrict__ wo)
{
    int gid = blockIdx.x * 256 + threadIdx.x;
    if (gid < BHT * CLEN) g_LmaxI[gid] = 0u;

    const float* src;
    size_t off;
    int local;
    if (gid < XN4) { src = x; local = gid; off = OFF_X; }
    else {
        int j = gid - XN4;
        int w = j >> 18;
        local = j & (WN4 - 1);
        src = (w == 0) ? wq : (w == 1) ? wk : (w == 2) ? wv : wo;
        off = OFF_W + (size_t)w * DM2E;
    }
    float4 a = ((const float4*)src)[local];
    __half2* hi2 = reinterpret_cast<__half2*>(g_hi + off) + 2 * local;
    hi2[0] = __halves2half2(__float2half(a.x), __float2half(a.y));
    hi2[1] = __halves2half2(__float2half(a.z), __float2half(a.w));
}

// ---------------------------------------------------------------------------
// Tensor-core GEMM, single-pass fp16 (R12-proven geometry).
// ---------------------------------------------------------------------------
__global__ __launch_bounds__(256, 2)
void gemm_mma(int aoff, int boff, const float* __restrict__ bias,
              const float* __restrict__ beta, int outsel, float* Outp, int qscale)
{
    extern __shared__ __align__(128) char smem_raw[];
    const uint32_t sb0 = smem_u32(smem_raw);

    float* Out = (outsel == 0) ? g_Q : (outsel == 1) ? g_K : (outsel == 2) ? g_V : Outp;

    const int tid = threadIdx.x;
    const int bn = blockIdx.x, bm = blockIdx.y;
    const int warp = tid >> 5, lane = tid & 31;
    const int wm = warp & 1, wn = warp >> 1;
    const int g = lane >> 2, tig = lane & 3;

    const char* a_h = (const char*)(g_hi + aoff) + (size_t)(bm * 128) * 2048;
    const char* b_h = (const char*)(g_hi + boff) + (size_t)(bn * 128) * 2048;

    float acc[4][4][4];
#pragma unroll
    for (int mi = 0; mi < 4; mi++)
#pragma unroll
        for (int ni = 0; ni < 4; ni++)
#pragma unroll
            for (int r = 0; r < 4; r++) acc[mi][ni][r] = 0.f;

    const int lrow0 = tid >> 2, lseg = tid & 3;

    const uint32_t a_lane = (uint32_t)(wm * 64 + (lane & 15)) * ROWB + ((lane >> 4) & 1) * 16;
    const uint32_t q4 = lane >> 3;
    const uint32_t b_lane = (uint32_t)(wn * 32 + ((q4 >> 1) & 1) * 8 + (lane & 7)) * ROWB
                          + (q4 & 1) * 16;

#define PREFETCH(kc) do { \
    uint32_t dstb = sb0 + ((kc) & 1) * STAGEB; \
    size_t kb = (size_t)(kc) * 64; \
    _Pragma("unroll") \
    for (int j = 0; j < 2; j++) { \
        int row = lrow0 + j * 64; \
        uint32_t doff = (uint32_t)row * ROWB + lseg * 16; \
        size_t soff = (size_t)row * 2048 + kb + lseg * 16; \
        CP16(dstb + 0     + doff, a_h + soff); \
        CP16(dstb + TILEB + doff, b_h + soff); \
    } \
    CP_COMMIT(); } while (0)

    PREFETCH(0);

    for (int kc = 0; kc < 32; kc++) {
        if (kc + 1 < 32) { PREFETCH(kc + 1); CP_WAIT1(); }
        else             { CP_WAIT0(); }
        __syncthreads();

        const uint32_t st = sb0 + (kc & 1) * STAGEB;

#pragma unroll
        for (int ks = 0; ks < 2; ks++) {
            uint32_t ah[4][4], bh[4][2];
            const uint32_t abase = st + a_lane + ks * 32;
#pragma unroll
            for (int mi = 0; mi < 4; mi++)
                LDSM4(ah[mi][0], ah[mi][1], ah[mi][2], ah[mi][3], abase + mi * (16 * ROWB));
            const uint32_t bbase = st + TILEB + b_lane + ks * 32;
            LDSM4(bh[0][0], bh[0][1], bh[1][0], bh[1][1], bbase);
            LDSM4(bh[2][0], bh[2][1], bh[3][0], bh[3][1], bbase + 16 * ROWB);

#pragma unroll
            for (int mi = 0; mi < 4; mi++)
#pragma unroll
                for (int ni = 0; ni < 4; ni++)
                    mma16816(acc[mi][ni], ah[mi], bh[ni]);
        }
        __syncthreads();
    }
#undef PREFETCH

    const int ncol0 = bn * 128 + wn * 32;
    float sc = qscale ? (1.0f / (8.0f * expf(beta[ncol0 >> 6]))) : 1.0f;
#pragma unroll
    for (int mi = 0; mi < 4; mi++) {
        int m0 = bm * 128 + wm * 64 + mi * 16 + g;
#pragma unroll
        for (int ni = 0; ni < 4; ni++) {
            int n0 = ncol0 + ni * 8 + tig * 2;
            float b0 = bias[n0], b1 = bias[n0 + 1];
            float2 v0, v1;
            v0.x = (acc[mi][ni][0] + b0) * sc;
            v0.y = (acc[mi][ni][1] + b1) * sc;
            v1.x = (acc[mi][ni][2] + b0) * sc;
            v1.y = (acc[mi][ni][3] + b1) * sc;
            *(float2*)(Out + (size_t)m0 * DMODEL + n0) = v0;
            *(float2*)(Out + (size_t)(m0 + 8) * DMODEL + n0) = v1;
        }
    }
}

// ---------------------------------------------------------------------------
// logits + fused per-(g,c) max
// ---------------------------------------------------------------------------
__global__ __launch_bounds__(128)
void k_logits(const float* __restrict__ qc)
{
    int g = blockIdx.y, h = g & 15, b = g >> 4;
    __shared__ float qsh[CLEN * DHEAD];
    __shared__ float redm[CLEN][128];
    for (int i = threadIdx.x; i < CLEN * DHEAD; i += 128)
        qsh[i] = qc[(i >> 6) * DMODEL + h * DHEAD + (i & 63)];
    __syncthreads();

    int tid = threadIdx.x;
    int s = blockIdx.x * 128 + tid;
    int m = s * BATCH + b;
    const float* kr = g_K + (size_t)m * DMODEL + h * DHEAD;
    float acc[CLEN];
#pragma unroll
    for (int c = 0; c < CLEN; c++) acc[c] = 0.f;
    for (int d = 0; d < DHEAD; d += 4) {
        float4 kv = *(const float4*)(kr + d);
#pragma unroll
        for (int c = 0; c < CLEN; c++) {
            acc[c] = fmaf(qsh[c * 64 + d + 0], kv.x, acc[c]);
            acc[c] = fmaf(qsh[c * 64 + d + 1], kv.y, acc[c]);
            acc[c] = fmaf(qsh[c * 64 + d + 2], kv.z, acc[c]);
            acc[c] = fmaf(qsh[c * 64 + d + 3], kv.w, acc[c]);
        }
    }
    float* wp = g_Wt + ((size_t)g * S_LEN + s) * CLEN;
#pragma unroll
    for (int c = 0; c < CLEN; c++) { wp[c] = acc[c]; redm[c][tid] = acc[c]; }
    __syncthreads();

    int w = tid >> 5, lane = tid & 31;
#pragma unroll
    for (int cc = 0; cc < 4; cc++) {
        int c = w * 4 + cc;
        float v = fmaxf(fmaxf(redm[c][lane], redm[c][lane + 32]),
                        fmaxf(redm[c][lane + 64], redm[c][lane + 96]));
        v = fmaxf(v, __shfl_xor_sync(0xffffffffu, v, 16));
        v = fmaxf(v, __shfl_xor_sync(0xffffffffu, v, 8));
        v = fmaxf(v, __shfl_xor_sync(0xffffffffu, v, 4));
        v = fmaxf(v, __shfl_xor_sync(0xffffffffu, v, 2));
        v = fmaxf(v, __shfl_xor_sync(0xffffffffu, v, 1));
        if (lane == 0) atomicMax(&g_LmaxI[g * CLEN + c], enc_max(v));
    }
}

// ---------------------------------------------------------------------------
// Chunk partial sums, barrier-free mainloop
// ---------------------------------------------------------------------------
__global__ __launch_bounds__(128)
void k_chunksum_mm()
{
    __shared__ float Wsh[64 * 20];
    int g = blockIdx.y, cx = blockIdx.x;
    int b = g >> 4, h = g & 15;
    int tid = threadIdx.x, d = tid;

    {
        int t = tid >> 1, c0 = (tid & 1) * 8;
#pragma unroll
        for (int j = 0; j < 8; j++) {
            int c = c0 + j;
            float lm = dec_max(g_LmaxI[g * CLEN + c]);
            float lg = g_Wt[((size_t)g * S_LEN + cx * 64 + t) * CLEN + c];
            Wsh[t * 20 + c] = expf(lg - lm);
        }
    }
    __syncthreads();

    const float* kvb = ((d < 64) ? g_K : g_V) + (size_t)b * DMODEL + h * DHEAD + (d & 63);
    float acc[16];
#pragma unroll
    for (int c = 0; c < 16; c++) acc[c] = 0.f;

    for (int t = 0; t < 64; t += 4) {
        float kvr[4];
#pragma unroll
        for (int i = 0; i < 4; i++)
            kvr[i] = kvb[(size_t)(cx * 64 + t + i) * 2048];
#pragma unroll
        for (int i = 0; i < 4; i++) {
            float4 wv[4];
            const float4* w4 = (const float4*)&Wsh[(t + i) * 20];
            wv[0] = w4[0]; wv[1] = w4[1]; wv[2] = w4[2]; wv[3] = w4[3];
            const float* wf = (const float*)wv;
            float kv = kvr[i];
#pragma unroll
            for (int c = 0; c < 16; c++) acc[c] = fmaf(wf[c], kv, acc[c]);
        }
    }
    float* ps = g_Psum + ((size_t)(g * NCH + cx) * CLEN) * 128;
#pragma unroll
    for (int c = 0; c < 16; c++) ps[c * 128 + d] = acc[c];
    if (tid < CLEN) {
        float r = 0.f;
        for (int t = 0; t < 64; t++) r += Wsh[t * 20 + tid];
        g_Pden[(g * NCH + cx) * CLEN + tid] = r;
    }
}

// ---------------------------------------------------------------------------
// In-place inclusive prefix over chunks (per g)
// ---------------------------------------------------------------------------
__global__ __launch_bounds__(128)
void k_prefix()
{
    int g = blockIdx.x, d = threadIdx.x;
    float run[16];
#pragma unroll
    for (int c = 0; c < 16; c++) run[c] = 0.f;
    for (int cx = 0; cx < NCH; cx++) {
        float* base = g_Psum + ((size_t)(g * NCH + cx) * CLEN) * 128;
#pragma unroll
        for (int c = 0; c < 16; c++) {
            run[c] += base[c * 128 + d];
            base[c * 128 + d] = run[c];
        }
    }
    if (d < CLEN) {
        float r = 0.f;
        for (int cx = 0; cx < NCH; cx++) {
            r += g_Pden[(g * NCH + cx) * CLEN + d];
            g_Pden[(g * NCH + cx) * CLEN + d] = r;
        }
    }
}

// ---------------------------------------------------------------------------
// Matrix-form scan + attention epilogue
// ---------------------------------------------------------------------------
__global__ __launch_bounds__(128)
void k_scan_mm()
{
    extern __shared__ float sm[];
    int g = blockIdx.y, cx = blockIdx.x;
    int b = g >> 4, h = g & 15;
    int tid = threadIdx.x;

    {
        int t = tid >> 1, c0 = (tid & 1) * 8;
#pragma unroll
        for (int j = 0; j < 8; j++) {
            int c = c0 + j;
            float lm = dec_max(g_LmaxI[g * CLEN + c]);
            float lg = g_Wt[((size_t)g * S_LEN + cx * 64 + t) * CLEN + c];
            sm[SCW + t * 20 + c] = expf(lg - lm);
        }
    }
#pragma unroll
    for (int i = 0; i < 8; i++) {
        int fidx = i * 128 + tid;
        int row = fidx >> 4, c4 = fidx & 15;
        int m = (cx * 64 + row) * BATCH + b;
        float4 qv = *(const float4*)(g_Q + (size_t)m * DMODEL + h * DHEAD + c4 * 4);
        sm[SCQ + row * 65 + c4 * 4 + 0] = qv.x;
        sm[SCQ + row * 65 + c4 * 4 + 1] = qv.y;
        sm[SCQ + row * 65 + c4 * 4 + 2] = qv.z;
        sm[SCQ + row * 65 + c4 * 4 + 3] = qv.w;
        float4 kv = *(const float4*)(g_K + (size_t)m * DMODEL + h * DHEAD + c4 * 4);
        sm[SCKT + (c4 * 4 + 0) * 68 + row] = kv.x;
        sm[SCKT + (c4 * 4 + 1) * 68 + row] = kv.y;
        sm[SCKT + (c4 * 4 + 2) * 68 + row] = kv.z;
        sm[SCKT + (c4 * 4 + 3) * 68 + row] = kv.w;
    }
    {
        int d = tid;
#pragma unroll
        for (int c = 0; c < CLEN; c++) {
            float v = 0.f;
            if (cx > 0)
                v = g_Psum[((size_t)(g * NCH + cx - 1) * CLEN + c) * 128 + d];
            sm[SCNB + c * 130 + d] = v;
        }
        if (tid < CLEN)
            sm[SCDEN + tid] = (cx > 0) ? g_Pden[(g * NCH + cx - 1) * CLEN + tid] : 0.f;
    }
    __syncthreads();

    {
        int slg = tid >> 3, tg = tid & 7;
        int sl0 = slg * 4, t0 = tg * 8;
        float acc[4][8];
#pragma unroll
        for (int i = 0; i < 4; i++)
#pragma unroll
            for (int j = 0; j < 8; j++) acc[i][j] = 0.f;
        for (int d = 0; d < 64; d++) {
            float q[4];
#pragma unroll
            for (int i = 0; i < 4; i++) q[i] = sm[SCQ + (sl0 + i) * 65 + d];
            float4 kv2[2];
            const float4* kt4 = (const float4*)&sm[SCKT + d * 68 + t0];
            kv2[0] = kt4[0]; kv2[1] = kt4[1];
            const float* kt = (const float*)kv2;
#pragma unroll
            for (int i = 0; i < 4; i++)
#pragma unroll
                for (int j = 0; j < 8; j++)
                    acc[i][j] = fmaf(q[i], kt[j], acc[i][j]);
        }
#pragma unroll
        for (int i = 0; i < 4; i++)
#pragma unroll
            for (int j = 0; j < 8; j++)
                sm[SCG + (sl0 + i) * 65 + t0 + j] = acc[i][j];
    }
    __syncthreads();

    {
        int sl = tid & 63, ch = tid >> 6, c0 = ch * 8;
        float a[8];
#pragma unroll
        for (int j = 0; j < 8; j++) a[j] = 0.f;
        for (int d = 0; d < 64; d++) {
            float q = sm[SCQ + sl * 65 + d];
#pragma unroll
            for (int j = 0; j < 8; j++)
                a[j] = fmaf(q, sm[SCNB + (c0 + j) * 130 + d], a[j]);
        }
        for (int t = 0; t <= sl; t++) {
            float gg = sm[SCG + sl * 65 + t];
            float4 wv[2];
            const float4* w4 = (const float4*)&sm[SCW + t * 20 + c0];
            wv[0] = w4[0]; wv[1] = w4[1];
            const float* wf = (const float*)wv;
#pragma unroll
            for (int j = 0; j < 8; j++)
                a[j] = fmaf(wf[j], gg, a[j]);
        }
#pragma unroll
        for (int j = 0; j < 8; j++) sm[SCC + sl * 20 + c0 + j] = a[j];

        if (tid < CLEN) {
            int c = tid;
            float r = sm[SCDEN + c];
            for (int t = 0; t < 64; t++) {
                r += sm[SCW + t * 20 + c];
                sm[SCD + t * 17 + c] = r;
            }
        }
    }
    __syncthreads();

#pragma unroll
    for (int i = 0; i < 8; i++) {
        int fidx = i * 128 + tid;
        int row = fidx >> 4, c4 = fidx & 15;
        int m = (cx * 64 + row) * BATCH + b;
        float4 vv = *(const float4*)(g_V + (size_t)m * DMODEL + h * DHEAD + c4 * 4);
        sm[SCQ + (c4 * 4 + 0) * 65 + row] = vv.x;
        sm[SCQ + (c4 * 4 + 1) * 65 + row] = vv.y;
        sm[SCQ + (c4 * 4 + 2) * 65 + row] = vv.z;
        sm[SCQ + (c4 * 4 + 3) * 65 + row] = vv.w;
    }
    if (tid < 64) {
        int sl = tid;
        float av[16], mx = -3.0e38f;
#pragma unroll
        for (int c = 0; c < 16; c++) {
            float aa = sm[SCC + sl * 20 + c] / sm[SCD + sl * 17 + c];
            av[c] = aa;
            mx = fmaxf(mx, aa);
        }
        float ssum = 0.f;
#pragma unroll
        for (int c = 0; c < 16; c++) { av[c] = expf(av[c] - mx); ssum += av[c]; }
        float inv = 1.0f / ssum;
#pragma unroll
        for (int c = 0; c < 16; c++)
            sm[SCC + sl * 20 + c] = av[c] * inv / sm[SCD + sl * 17 + c];
    }
    __syncthreads();

    {
        int dp = tid & 63, slh = tid >> 6;
        float num[16];
#pragma unroll
        for (int c = 0; c < 16; c++) num[c] = sm[SCNB + c * 130 + 64 + dp];
        if (slh) {
            for (int t = 0; t < 32; t++) {
                float kv = sm[SCQ + dp * 65 + t];
                float4 wv[4];
                const float4* w4 = (const float4*)&sm[SCW + t * 20];
                wv[0] = w4[0]; wv[1] = w4[1]; wv[2] = w4[2]; wv[3] = w4[3];
                const float* wf = (const float*)wv;
#pragma unroll
                for (int c = 0; c < 16; c++) num[c] = fmaf(wf[c], kv, num[c]);
            }
        }
        for (int sl = slh * 32; sl < slh * 32 + 32; sl++) {
            float kv = sm[SCQ + dp * 65 + sl];
            float4 wv[4], pv[4];
            const float4* w4 = (const float4*)&sm[SCW + sl * 20];
            const float4* p4 = (const float4*)&sm[SCC + sl * 20];
            wv[0] = w4[0]; wv[1] = w4[1]; wv[2] = w4[2]; wv[3] = w4[3];
            pv[0] = p4[0]; pv[1] = p4[1]; pv[2] = p4[2]; pv[3] = p4[3];
            const float* wf = (const float*)wv;
            const float* pf = (const float*)pv;
            float o = 0.f;
#pragma unroll
            for (int c = 0; c < 16; c++) {
                num[c] = fmaf(wf[c], kv, num[c]);
                o = fmaf(pf[c], num[c], o);
            }
            int m = (cx * 64 + sl) * BATCH + b;
            g_hi[(size_t)OFF_O + (size_t)m * DMODEL + h * DHEAD + dp] = __float2half(o);
        }
    }
}

// ---------------------------------------------------------------------------
// Stream/event init at static-construction time
// ---------------------------------------------------------------------------
static cudaStream_t g_sQ, g_sV;
static cudaEvent_t g_evA, g_evQ, g_evV;
namespace {
struct InitRes {
    InitRes() {
        cudaFuncSetAttribute(gemm_mma, cudaFuncAttributeMaxDynamicSharedMemorySize, GSMEM);
        cudaFuncSetAttribute(k_scan_mm, cudaFuncAttributeMaxDynamicSharedMemorySize, SCTOT * 4);
        cudaStreamCreateWithFlags(&g_sQ, cudaStreamNonBlocking);
        cudaStreamCreateWithFlags(&g_sV, cudaStreamNonBlocking);
        cudaEventCreateWithFlags(&g_evA, cudaEventDisableTiming);
        cudaEventCreateWithFlags(&g_evQ, cudaEventDisableTiming);
        cudaEventCreateWithFlags(&g_evV, cudaEventDisableTiming);
    }
};
static InitRes g_init_res;
}

// ---------------------------------------------------------------------------
extern "C" void kernel_launch(void* const* d_in, const int* in_sizes, int n_in,
                              void* d_out, int out_size)
{
    const float* x    = (const float*)d_in[0];
    const float* q_c  = (const float*)d_in[1];
    const float* beta = (const float*)d_in[2];
    const float* Wq   = (const float*)d_in[3];
    const float* bq   = (const float*)d_in[4];
    const float* Wk   = (const float*)d_in[5];
    const float* bk   = (const float*)d_in[6];
    const float* Wv   = (const float*)d_in[7];
    const float* bv   = (const float*)d_in[8];
    const float* Wo   = (const float*)d_in[9];
    const float* bo   = (const float*)d_in[10];
    float* out = (float*)d_out;

    const int TOTQ = XN4 + 4 * WN4;

    // 1) fused convert (main stream)
    k_split_all<<<TOTQ / 256, 256>>>(x, Wq, Wk, Wv, Wo);
    cudaEventRecord(g_evA, 0);

    // 2) Q projection on stream sQ (needed only by k_scan)
    cudaStreamWaitEvent(g_sQ, g_evA, 0);
    gemm_mma<<<dim3(8, 32), 256, GSMEM, g_sQ>>>(OFF_X, OFF_W + 0 * DM2E, bq, beta, 0, nullptr, 1);
    cudaEventRecord(g_evQ, g_sQ);

    // 3) V projection on stream sV (needed only by k_chunksum onward)
    cudaStreamWaitEvent(g_sV, g_evA, 0);
    gemm_mma<<<dim3(8, 32), 256, GSMEM, g_sV>>>(OFF_X, OFF_W + 2 * DM2E, bv, beta, 2, nullptr, 0);
    cudaEventRecord(g_evV, g_sV);

    // 4) main chain: K projection -> logits (needs only K)
    gemm_mma<<<dim3(8, 32), 256, GSMEM>>>(OFF_X, OFF_W + 1 * DM2E, bk, beta, 1, nullptr, 0);
    k_logits<<<dim3(S_LEN / 128, BHT), 128>>>(q_c);

    // 5) join V, run chunk sums + prefix
    cudaStreamWaitEvent(0, g_evV, 0);
    k_chunksum_mm<<<dim3(NCH, BHT), 128>>>();
    k_prefix<<<BHT, 128>>>();

    // 6) join Q, scan (writes fp16 O), output projection
    cudaStreamWaitEvent(0, g_evQ, 0);
    k_scan_mm<<<dim3(NCH, BHT), 128, SCTOT * 4>>>();
    gemm_mma<<<dim3(8, 32), 256, GSMEM>>>(OFF_O, OFF_W + 3 * DM2E, bo, beta, 3, out, 0);
}

// round 15
// speedup vs baseline: 1.1819x; 1.0660x over previous
#include <cuda_runtime.h>
#include <cuda_fp16.h>
#include <math.h>
#include <stdint.h>

// Problem constants
#define S_LEN   2048
#define BATCH   2
#define DMODEL  1024
#define NHEADS  16
#define DHEAD   64
#define CLEN    16
#define BHT     32
#define MROWS   4096
#define NCH     32
#define CHLEN   64
#define DM2E    (DMODEL * DMODEL)

// fp16 storage offsets (elements)
#define OFF_X   0
#define OFF_W   (MROWS * DMODEL)
#define OFF_O   (OFF_W + 4 * DMODEL * DMODEL)
#define BF_TOT  (OFF_O + MROWS * DMODEL)

#define XN4     (MROWS * DMODEL / 4)
#define WN4     (DMODEL * DMODEL / 4)

// GEMM smem geometry: 2 tiles (A,B) x 128 rows x 80B/row per stage, 4 stages
#define ROWB    80
#define TILEB   (128 * ROWB)
#define STAGEB  (2 * TILEB)
#define NSTAGE  4
#define GSMEM   (NSTAGE * STAGEB)   // 81920 bytes -> still 2 CTAs/SM

// scan smem layout (floats)
#define SCQ     0
#define SCKT    4160
#define SCG     8512
#define SCW     12672
#define SCC     13952
#define SCD     15232
#define SCNB    16320
#define SCDEN   18400
#define SCTOT   18416

// Scratch
__device__ __align__(256) float g_Q[MROWS * DMODEL];
__device__ __align__(256) float g_K[MROWS * DMODEL];
__device__ __align__(256) float g_V[MROWS * DMODEL];
__device__ __align__(256) float g_Wt[BHT * S_LEN * CLEN];
__device__ __align__(256) unsigned int g_LmaxI[BHT * CLEN];
__device__ __align__(256) float g_Psum[BHT * NCH * CLEN * 128];
__device__ __align__(256) float g_Pden[BHT * NCH * CLEN];
__device__ __align__(256) __half g_hi[BF_TOT];

// ---------------------------------------------------------------------------
__device__ __forceinline__ uint32_t smem_u32(const void* p) {
    uint32_t a;
    asm("{ .reg .u64 t; cvta.to.shared.u64 t, %1; cvt.u32.u64 %0, t; }" : "=r"(a) : "l"(p));
    return a;
}
#define CP16(dst, src) \
    asm volatile("cp.async.cg.shared.global [%0], [%1], 16;" :: "r"(dst), "l"(src))
#define CP_COMMIT() asm volatile("cp.async.commit_group;" ::: "memory")
#define CP_WAIT2()  asm volatile("cp.async.wait_group 2;" ::: "memory")

#define LDSM4(r0, r1, r2, r3, addr) \
    asm volatile("ldmatrix.sync.aligned.m8n8.x4.shared.b16 {%0,%1,%2,%3}, [%4];" \
        : "=r"(r0), "=r"(r1), "=r"(r2), "=r"(r3) : "r"(addr))

__device__ __forceinline__ void mma16816(float* d, const uint32_t* a, const uint32_t* b)
{
    asm volatile(
        "mma.sync.aligned.m16n8k16.row.col.f32.f16.f16.f32 "
        "{%0,%1,%2,%3}, {%4,%5,%6,%7}, {%8,%9}, {%0,%1,%2,%3};"
        : "+f"(d[0]), "+f"(d[1]), "+f"(d[2]), "+f"(d[3])
        : "r"(a[0]), "r"(a[1]), "r"(a[2]), "r"(a[3]), "r"(b[0]), "r"(b[1]));
}

__device__ __forceinline__ unsigned int enc_max(float f) {
    unsigned int u = __float_as_uint(f);
    return (u & 0x80000000u) ? ~u : (u | 0x80000000u);
}
__device__ __forceinline__ float dec_max(unsigned int u) {
    return (u & 0x80000000u) ? __uint_as_float(u ^ 0x80000000u) : __uint_as_float(~u);
}

// ---------------------------------------------------------------------------
// Fused convert: x + 4 weights -> fp16; also zero-inits g_LmaxI.
// ---------------------------------------------------------------------------
__global__ __launch_bounds__(256)
void k_split_all(const float* __restrict__ x,  const float* __restrict__ wq,
                 const float* __restrict__ wk, const float* __restrict__ wv,
                 const float* __restrict__ wo)
{
    int gid = blockIdx.x * 256 + threadIdx.x;
    if (gid < BHT * CLEN) g_LmaxI[gid] = 0u;

    const float* src;
    size_t off;
    int local;
    if (gid < XN4) { src = x; local = gid; off = OFF_X; }
    else {
        int j = gid - XN4;
        int w = j >> 18;
        local = j & (WN4 - 1);
        src = (w == 0) ? wq : (w == 1) ? wk : (w == 2) ? wv : wo;
        off = OFF_W + (size_t)w * DM2E;
    }
    float4 a = ((const float4*)src)[local];
    __half2* hi2 = reinterpret_cast<__half2*>(g_hi + off) + 2 * local;
    hi2[0] = __halves2half2(__float2half(a.x), __float2half(a.y));
    hi2[1] = __halves2half2(__float2half(a.z), __float2half(a.w));
}

// ---------------------------------------------------------------------------
// Tensor-core GEMM, single-pass fp16, 4-stage cp.async, ONE barrier per kc.
// ---------------------------------------------------------------------------
__global__ __launch_bounds__(256, 2)
void gemm_mma(int aoff, int boff, const float* __restrict__ bias,
              const float* __restrict__ beta, int outsel, float* Outp, int qscale)
{
    extern __shared__ __align__(128) char smem_raw[];
    const uint32_t sb0 = smem_u32(smem_raw);

    float* Out = (outsel == 0) ? g_Q : (outsel == 1) ? g_K : (outsel == 2) ? g_V : Outp;

    const int tid = threadIdx.x;
    const int bn = blockIdx.x, bm = blockIdx.y;
    const int warp = tid >> 5, lane = tid & 31;
    const int wm = warp & 1, wn = warp >> 1;
    const int g = lane >> 2, tig = lane & 3;

    const char* a_h = (const char*)(g_hi + aoff) + (size_t)(bm * 128) * 2048;
    const char* b_h = (const char*)(g_hi + boff) + (size_t)(bn * 128) * 2048;

    float acc[4][4][4];
#pragma unroll
    for (int mi = 0; mi < 4; mi++)
#pragma unroll
        for (int ni = 0; ni < 4; ni++)
#pragma unroll
            for (int r = 0; r < 4; r++) acc[mi][ni][r] = 0.f;

    const int lrow0 = tid >> 2, lseg = tid & 3;

    const uint32_t a_lane = (uint32_t)(wm * 64 + (lane & 15)) * ROWB + ((lane >> 4) & 1) * 16;
    const uint32_t q4 = lane >> 3;
    const uint32_t b_lane = (uint32_t)(wn * 32 + ((q4 >> 1) & 1) * 8 + (lane & 7)) * ROWB
                          + (q4 & 1) * 16;

// Always commits (keeps wait_group counts exact at the tail).
#define PREFETCH(kc) do { \
    if ((kc) < 32) { \
        uint32_t dstb = sb0 + ((kc) & 3) * STAGEB; \
        size_t kb = (size_t)(kc) * 64; \
        _Pragma("unroll") \
        for (int j = 0; j < 2; j++) { \
            int row = lrow0 + j * 64; \
            uint32_t doff = (uint32_t)row * ROWB + lseg * 16; \
            size_t soff = (size_t)row * 2048 + kb + lseg * 16; \
            CP16(dstb + 0     + doff, a_h + soff); \
            CP16(dstb + TILEB + doff, b_h + soff); \
        } \
    } \
    CP_COMMIT(); } while (0)

    PREFETCH(0);
    PREFETCH(1);
    PREFETCH(2);

    for (int kc = 0; kc < 32; kc++) {
        CP_WAIT2();
        __syncthreads();
        PREFETCH(kc + 3);   // writes stage (kc-1)&3; its reads finished pre-barrier

        const uint32_t st = sb0 + (kc & 3) * STAGEB;

#pragma unroll
        for (int ks = 0; ks < 2; ks++) {
            uint32_t ah[4][4], bh[4][2];
            const uint32_t abase = st + a_lane + ks * 32;
#pragma unroll
            for (int mi = 0; mi < 4; mi++)
                LDSM4(ah[mi][0], ah[mi][1], ah[mi][2], ah[mi][3], abase + mi * (16 * ROWB));
            const uint32_t bbase = st + TILEB + b_lane + ks * 32;
            LDSM4(bh[0][0], bh[0][1], bh[1][0], bh[1][1], bbase);
            LDSM4(bh[2][0], bh[2][1], bh[3][0], bh[3][1], bbase + 16 * ROWB);

#pragma unroll
            for (int mi = 0; mi < 4; mi++)
#pragma unroll
                for (int ni = 0; ni < 4; ni++)
                    mma16816(acc[mi][ni], ah[mi], bh[ni]);
        }
    }
#undef PREFETCH

    const int ncol0 = bn * 128 + wn * 32;
    float sc = qscale ? (1.0f / (8.0f * expf(beta[ncol0 >> 6]))) : 1.0f;
#pragma unroll
    for (int mi = 0; mi < 4; mi++) {
        int m0 = bm * 128 + wm * 64 + mi * 16 + g;
#pragma unroll
        for (int ni = 0; ni < 4; ni++) {
            int n0 = ncol0 + ni * 8 + tig * 2;
            float b0 = bias[n0], b1 = bias[n0 + 1];
            float2 v0, v1;
            v0.x = (acc[mi][ni][0] + b0) * sc;
            v0.y = (acc[mi][ni][1] + b1) * sc;
            v1.x = (acc[mi][ni][2] + b0) * sc;
            v1.y = (acc[mi][ni][3] + b1) * sc;
            *(float2*)(Out + (size_t)m0 * DMODEL + n0) = v0;
            *(float2*)(Out + (size_t)(m0 + 8) * DMODEL + n0) = v1;
        }
    }
}

// ---------------------------------------------------------------------------
// logits + fused per-(g,c) max
// ---------------------------------------------------------------------------
__global__ __launch_bounds__(128)
void k_logits(const float* __restrict__ qc)
{
    int g = blockIdx.y, h = g & 15, b = g >> 4;
    __shared__ float qsh[CLEN * DHEAD];
    __shared__ float redm[CLEN][128];
    for (int i = threadIdx.x; i < CLEN * DHEAD; i += 128)
        qsh[i] = qc[(i >> 6) * DMODEL + h * DHEAD + (i & 63)];
    __syncthreads();

    int tid = threadIdx.x;
    int s = blockIdx.x * 128 + tid;
    int m = s * BATCH + b;
    const float* kr = g_K + (size_t)m * DMODEL + h * DHEAD;
    float acc[CLEN];
#pragma unroll
    for (int c = 0; c < CLEN; c++) acc[c] = 0.f;
    for (int d = 0; d < DHEAD; d += 4) {
        float4 kv = *(const float4*)(kr + d);
#pragma unroll
        for (int c = 0; c < CLEN; c++) {
            acc[c] = fmaf(qsh[c * 64 + d + 0], kv.x, acc[c]);
            acc[c] = fmaf(qsh[c * 64 + d + 1], kv.y, acc[c]);
            acc[c] = fmaf(qsh[c * 64 + d + 2], kv.z, acc[c]);
            acc[c] = fmaf(qsh[c * 64 + d + 3], kv.w, acc[c]);
        }
    }
    float* wp = g_Wt + ((size_t)g * S_LEN + s) * CLEN;
#pragma unroll
    for (int c = 0; c < CLEN; c++) { wp[c] = acc[c]; redm[c][tid] = acc[c]; }
    __syncthreads();

    int w = tid >> 5, lane = tid & 31;
#pragma unroll
    for (int cc = 0; cc < 4; cc++) {
        int c = w * 4 + cc;
        float v = fmaxf(fmaxf(redm[c][lane], redm[c][lane + 32]),
                        fmaxf(redm[c][lane + 64], redm[c][lane + 96]));
        v = fmaxf(v, __shfl_xor_sync(0xffffffffu, v, 16));
        v = fmaxf(v, __shfl_xor_sync(0xffffffffu, v, 8));
        v = fmaxf(v, __shfl_xor_sync(0xffffffffu, v, 4));
        v = fmaxf(v, __shfl_xor_sync(0xffffffffu, v, 2));
        v = fmaxf(v, __shfl_xor_sync(0xffffffffu, v, 1));
        if (lane == 0) atomicMax(&g_LmaxI[g * CLEN + c], enc_max(v));
    }
}

// ---------------------------------------------------------------------------
// Chunk partial sums, barrier-free mainloop
// ---------------------------------------------------------------------------
__global__ __launch_bounds__(128)
void k_chunksum_mm()
{
    __shared__ float Wsh[64 * 20];
    int g = blockIdx.y, cx = blockIdx.x;
    int b = g >> 4, h = g & 15;
    int tid = threadIdx.x, d = tid;

    {
        int t = tid >> 1, c0 = (tid & 1) * 8;
#pragma unroll
        for (int j = 0; j < 8; j++) {
            int c = c0 + j;
            float lm = dec_max(g_LmaxI[g * CLEN + c]);
            float lg = g_Wt[((size_t)g * S_LEN + cx * 64 + t) * CLEN + c];
            Wsh[t * 20 + c] = expf(lg - lm);
        }
    }
    __syncthreads();

    const float* kvb = ((d < 64) ? g_K : g_V) + (size_t)b * DMODEL + h * DHEAD + (d & 63);
    float acc[16];
#pragma unroll
    for (int c = 0; c < 16; c++) acc[c] = 0.f;

    for (int t = 0; t < 64; t += 4) {
        float kvr[4];
#pragma unroll
        for (int i = 0; i < 4; i++)
            kvr[i] = kvb[(size_t)(cx * 64 + t + i) * 2048];
#pragma unroll
        for (int i = 0; i < 4; i++) {
            float4 wv[4];
            const float4* w4 = (const float4*)&Wsh[(t + i) * 20];
            wv[0] = w4[0]; wv[1] = w4[1]; wv[2] = w4[2]; wv[3] = w4[3];
            const float* wf = (const float*)wv;
            float kv = kvr[i];
#pragma unroll
            for (int c = 0; c < 16; c++) acc[c] = fmaf(wf[c], kv, acc[c]);
        }
    }
    float* ps = g_Psum + ((size_t)(g * NCH + cx) * CLEN) * 128;
#pragma unroll
    for (int c = 0; c < 16; c++) ps[c * 128 + d] = acc[c];
    if (tid < CLEN) {
        float r = 0.f;
        for (int t = 0; t < 64; t++) r += Wsh[t * 20 + tid];
        g_Pden[(g * NCH + cx) * CLEN + tid] = r;
    }
}

// ---------------------------------------------------------------------------
// In-place inclusive prefix over chunks (per g)
// ---------------------------------------------------------------------------
__global__ __launch_bounds__(128)
void k_prefix()
{
    int g = blockIdx.x, d = threadIdx.x;
    float run[16];
#pragma unroll
    for (int c = 0; c < 16; c++) run[c] = 0.f;
    for (int cx = 0; cx < NCH; cx++) {
        float* base = g_Psum + ((size_t)(g * NCH + cx) * CLEN) * 128;
#pragma unroll
        for (int c = 0; c < 16; c++) {
            run[c] += base[c * 128 + d];
            base[c * 128 + d] = run[c];
        }
    }
    if (d < CLEN) {
        float r = 0.f;
        for (int cx = 0; cx < NCH; cx++) {
            r += g_Pden[(g * NCH + cx) * CLEN + d];
            g_Pden[(g * NCH + cx) * CLEN + d] = r;
        }
    }
}

// ---------------------------------------------------------------------------
// Matrix-form scan + attention epilogue
// ---------------------------------------------------------------------------
__global__ __launch_bounds__(128)
void k_scan_mm()
{
    extern __shared__ float sm[];
    int g = blockIdx.y, cx = blockIdx.x;
    int b = g >> 4, h = g & 15;
    int tid = threadIdx.x;

    {
        int t = tid >> 1, c0 = (tid & 1) * 8;
#pragma unroll
        for (int j = 0; j < 8; j++) {
            int c = c0 + j;
            float lm = dec_max(g_LmaxI[g * CLEN + c]);
            float lg = g_Wt[((size_t)g * S_LEN + cx * 64 + t) * CLEN + c];
            sm[SCW + t * 20 + c] = expf(lg - lm);
        }
    }
#pragma unroll
    for (int i = 0; i < 8; i++) {
        int fidx = i * 128 + tid;
        int row = fidx >> 4, c4 = fidx & 15;
        int m = (cx * 64 + row) * BATCH + b;
        float4 qv = *(const float4*)(g_Q + (size_t)m * DMODEL + h * DHEAD + c4 * 4);
        sm[SCQ + row * 65 + c4 * 4 + 0] = qv.x;
        sm[SCQ + row * 65 + c4 * 4 + 1] = qv.y;
        sm[SCQ + row * 65 + c4 * 4 + 2] = qv.z;
        sm[SCQ + row * 65 + c4 * 4 + 3] = qv.w;
        float4 kv = *(const float4*)(g_K + (size_t)m * DMODEL + h * DHEAD + c4 * 4);
        sm[SCKT + (c4 * 4 + 0) * 68 + row] = kv.x;
        sm[SCKT + (c4 * 4 + 1) * 68 + row] = kv.y;
        sm[SCKT + (c4 * 4 + 2) * 68 + row] = kv.z;
        sm[SCKT + (c4 * 4 + 3) * 68 + row] = kv.w;
    }
    {
        int d = tid;
#pragma unroll
        for (int c = 0; c < CLEN; c++) {
            float v = 0.f;
            if (cx > 0)
                v = g_Psum[((size_t)(g * NCH + cx - 1) * CLEN + c) * 128 + d];
            sm[SCNB + c * 130 + d] = v;
        }
        if (tid < CLEN)
            sm[SCDEN + tid] = (cx > 0) ? g_Pden[(g * NCH + cx - 1) * CLEN + tid] : 0.f;
    }
    __syncthreads();

    {
        int slg = tid >> 3, tg = tid & 7;
        int sl0 = slg * 4, t0 = tg * 8;
        float acc[4][8];
#pragma unroll
        for (int i = 0; i < 4; i++)
#pragma unroll
            for (int j = 0; j < 8; j++) acc[i][j] = 0.f;
        for (int d = 0; d < 64; d++) {
            float q[4];
#pragma unroll
            for (int i = 0; i < 4; i++) q[i] = sm[SCQ + (sl0 + i) * 65 + d];
            float4 kv2[2];
            const float4* kt4 = (const float4*)&sm[SCKT + d * 68 + t0];
            kv2[0] = kt4[0]; kv2[1] = kt4[1];
            const float* kt = (const float*)kv2;
#pragma unroll
            for (int i = 0; i < 4; i++)
#pragma unroll
                for (int j = 0; j < 8; j++)
                    acc[i][j] = fmaf(q[i], kt[j], acc[i][j]);
        }
#pragma unroll
        for (int i = 0; i < 4; i++)
#pragma unroll
            for (int j = 0; j < 8; j++)
                sm[SCG + (sl0 + i) * 65 + t0 + j] = acc[i][j];
    }
    __syncthreads();

    {
        int sl = tid & 63, ch = tid >> 6, c0 = ch * 8;
        float a[8];
#pragma unroll
        for (int j = 0; j < 8; j++) a[j] = 0.f;
        for (int d = 0; d < 64; d++) {
            float q = sm[SCQ + sl * 65 + d];
#pragma unroll
            for (int j = 0; j < 8; j++)
                a[j] = fmaf(q, sm[SCNB + (c0 + j) * 130 + d], a[j]);
        }
        for (int t = 0; t <= sl; t++) {
            float gg = sm[SCG + sl * 65 + t];
            float4 wv[2];
            const float4* w4 = (const float4*)&sm[SCW + t * 20 + c0];
            wv[0] = w4[0]; wv[1] = w4[1];
            const float* wf = (const float*)wv;
#pragma unroll
            for (int j = 0; j < 8; j++)
                a[j] = fmaf(wf[j], gg, a[j]);
        }
#pragma unroll
        for (int j = 0; j < 8; j++) sm[SCC + sl * 20 + c0 + j] = a[j];

        if (tid < CLEN) {
            int c = tid;
            float r = sm[SCDEN + c];
            for (int t = 0; t < 64; t++) {
                r += sm[SCW + t * 20 + c];
                sm[SCD + t * 17 + c] = r;
            }
        }
    }
    __syncthreads();

#pragma unroll
    for (int i = 0; i < 8; i++) {
        int fidx = i * 128 + tid;
        int row = fidx >> 4, c4 = fidx & 15;
        int m = (cx * 64 + row) * BATCH + b;
        float4 vv = *(const float4*)(g_V + (size_t)m * DMODEL + h * DHEAD + c4 * 4);
        sm[SCQ + (c4 * 4 + 0) * 65 + row] = vv.x;
        sm[SCQ + (c4 * 4 + 1) * 65 + row] = vv.y;
        sm[SCQ + (c4 * 4 + 2) * 65 + row] = vv.z;
        sm[SCQ + (c4 * 4 + 3) * 65 + row] = vv.w;
    }
    if (tid < 64) {
        int sl = tid;
        float av[16], mx = -3.0e38f;
#pragma unroll
        for (int c = 0; c < 16; c++) {
            float aa = sm[SCC + sl * 20 + c] / sm[SCD + sl * 17 + c];
            av[c] = aa;
            mx = fmaxf(mx, aa);
        }
        float ssum = 0.f;
#pragma unroll
        for (int c = 0; c < 16; c++) { av[c] = expf(av[c] - mx); ssum += av[c]; }
        float inv = 1.0f / ssum;
#pragma unroll
        for (int c = 0; c < 16; c++)
            sm[SCC + sl * 20 + c] = av[c] * inv / sm[SCD + sl * 17 + c];
    }
    __syncthreads();

    {
        int dp = tid & 63, slh = tid >> 6;
        float num[16];
#pragma unroll
        for (int c = 0; c < 16; c++) num[c] = sm[SCNB + c * 130 + 64 + dp];
        if (slh) {
            for (int t = 0; t < 32; t++) {
                float kv = sm[SCQ + dp * 65 + t];
                float4 wv[4];
                const float4* w4 = (const float4*)&sm[SCW + t * 20];
                wv[0] = w4[0]; wv[1] = w4[1]; wv[2] = w4[2]; wv[3] = w4[3];
                const float* wf = (const float*)wv;
#pragma unroll
                for (int c = 0; c < 16; c++) num[c] = fmaf(wf[c], kv, num[c]);
            }
        }
        for (int sl = slh * 32; sl < slh * 32 + 32; sl++) {
            float kv = sm[SCQ + dp * 65 + sl];
            float4 wv[4], pv[4];
            const float4* w4 = (const float4*)&sm[SCW + sl * 20];
            const float4* p4 = (const float4*)&sm[SCC + sl * 20];
            wv[0] = w4[0]; wv[1] = w4[1]; wv[2] = w4[2]; wv[3] = w4[3];
            pv[0] = p4[0]; pv[1] = p4[1]; pv[2] = p4[2]; pv[3] = p4[3];
            const float* wf = (const float*)wv;
            const float* pf = (const float*)pv;
            float o = 0.f;
#pragma unroll
            for (int c = 0; c < 16; c++) {
                num[c] = fmaf(wf[c], kv, num[c]);
                o = fmaf(pf[c], num[c], o);
            }
            int m = (cx * 64 + sl) * BATCH + b;
            g_hi[(size_t)OFF_O + (size_t)m * DMODEL + h * DHEAD + dp] = __float2half(o);
        }
    }
}

// ---------------------------------------------------------------------------
// Stream/event init at static-construction time
// ---------------------------------------------------------------------------
static cudaStream_t g_sQ, g_sV;
static cudaEvent_t g_evA, g_evQ, g_evV;
namespace {
struct InitRes {
    InitRes() {
        cudaFuncSetAttribute(gemm_mma, cudaFuncAttributeMaxDynamicSharedMemorySize, GSMEM);
        cudaFuncSetAttribute(k_scan_mm, cudaFuncAttributeMaxDynamicSharedMemorySize, SCTOT * 4);
        cudaStreamCreateWithFlags(&g_sQ, cudaStreamNonBlocking);
        cudaStreamCreateWithFlags(&g_sV, cudaStreamNonBlocking);
        cudaEventCreateWithFlags(&g_evA, cudaEventDisableTiming);
        cudaEventCreateWithFlags(&g_evQ, cudaEventDisableTiming);
        cudaEventCreateWithFlags(&g_evV, cudaEventDisableTiming);
    }
};
static InitRes g_init_res;
}

// ---------------------------------------------------------------------------
extern "C" void kernel_launch(void* const* d_in, const int* in_sizes, int n_in,
                              void* d_out, int out_size)
{
    const float* x    = (const float*)d_in[0];
    const float* q_c  = (const float*)d_in[1];
    const float* beta = (const float*)d_in[2];
    const float* Wq   = (const float*)d_in[3];
    const float* bq   = (const float*)d_in[4];
    const float* Wk   = (const float*)d_in[5];
    const float* bk   = (const float*)d_in[6];
    const float* Wv   = (const float*)d_in[7];
    const float* bv   = (const float*)d_in[8];
    const float* Wo   = (const float*)d_in[9];
    const float* bo   = (const float*)d_in[10];
    float* out = (float*)d_out;

    const int TOTQ = XN4 + 4 * WN4;

    k_split_all<<<TOTQ / 256, 256>>>(x, Wq, Wk, Wv, Wo);
    cudaEventRecord(g_evA, 0);

    cudaStreamWaitEvent(g_sQ, g_evA, 0);
    gemm_mma<<<dim3(8, 32), 256, GSMEM, g_sQ>>>(OFF_X, OFF_W + 0 * DM2E, bq, beta, 0, nullptr, 1);
    cudaEventRecord(g_evQ, g_sQ);

    cudaStreamWaitEvent(g_sV, g_evA, 0);
    gemm_mma<<<dim3(8, 32), 256, GSMEM, g_sV>>>(OFF_X, OFF_W + 2 * DM2E, bv, beta, 2, nullptr, 0);
    cudaEventRecord(g_evV, g_sV);

    gemm_mma<<<dim3(8, 32), 256, GSMEM>>>(OFF_X, OFF_W + 1 * DM2E, bk, beta, 1, nullptr, 0);
    k_logits<<<dim3(S_LEN / 128, BHT), 128>>>(q_c);

    cudaStreamWaitEvent(0, g_evV, 0);
    k_chunksum_mm<<<dim3(NCH, BHT), 128>>>();
    k_prefix<<<BHT, 128>>>();

    cudaStreamWaitEvent(0, g_evQ, 0);
    k_scan_mm<<<dim3(NCH, BHT), 128, SCTOT * 4>>>();
    gemm_mma<<<dim3(8, 32), 256, GSMEM>>>(OFF_O, OFF_W + 3 * DM2E, bo, beta, 3, out, 0);
}